// round 11
// baseline (speedup 1.0000x reference)
#include <cuda_runtime.h>
#include <cstdint>

#define NN 64
#define NMAT 4096
#define GRID_P 760             // 5 blocks x 152 SMs: one resident wave
#define VAPPS 4                // + rowsum init = 5 applications total
#define RP 68                  // stage row pitch (words)

__device__ float g_acc[NN];
__device__ unsigned int g_ticket;

typedef unsigned long long u64;

__device__ __forceinline__ u64 ffma2(u64 a, u64 b, u64 c) {
    u64 d;
    asm("fma.rn.f32x2 %0, %1, %2, %3;" : "=l"(d) : "l"(a), "l"(b), "l"(c));
    return d;
}
__device__ __forceinline__ u64 fadd2(u64 a, u64 b) {
    u64 d;
    asm("add.rn.f32x2 %0, %1, %2;" : "=l"(d) : "l"(a), "l"(b));
    return d;
}
__device__ __forceinline__ void cp16(uint32_t dst, const void* src) {
    asm volatile("cp.async.cg.shared.global [%0], [%1], 16;" :: "r"(dst), "l"(src));
}
__device__ __forceinline__ u64 pack(float lo, float hi) {
    float2 f = make_float2(lo, hi);
    return *reinterpret_cast<u64*>(&f);
}

// Stream one 16KB matrix into a pitched smem tile (coalesced gmem; smem
// store banks 4*((r+j) mod 8): conflict-free).
__device__ __forceinline__ void issue_tile(float* bufp, const float* M, int t) {
    uint32_t b32 = (uint32_t)__cvta_generic_to_shared(bufp);
    const float4* src = reinterpret_cast<const float4*>(M);
#pragma unroll
    for (int i = 0; i < 4; ++i) {
        const int c = i * 256 + t;
        const int r = c >> 4, j = c & 15;
        cp16(b32 + (uint32_t)(r * RP + j * 4) * 4u, src + c);
    }
}

// lane = q*8 + k'; warp w owns rows 8w..8w+7 (all four quarters).
//  - tile reads: per quarter-warp phase q is fixed, k' spans 0..7 -> the 8
//    LDS.128 lanes cover 8 distinct 16B slots of a 128B window: conflict-free.
//  - v reads: address 16q+4i is phase-uniform -> pure broadcast, ONE v array.
//  - reduce: rows' quarter partners are lanes {k',k'+8,k'+16,k'+24} ->
//    two shfl_xor (8,16); q==0 lane stores v[k] (8 distinct banks).
// One barrier per matvec; persistent grid + cp.async double buffer.
__global__ __launch_bounds__(256, 5)
void power_kernel(const float* __restrict__ x,
                  const float* __restrict__ wt,
                  const float* __restrict__ rc,
                  float* __restrict__ out)
{
    const int t    = threadIdx.x;
    const int lane = t & 31;
    const int w    = t >> 5;
    const int q    = lane >> 3;        // quarter (uniform per phase)
    const int k    = w * 8 + (lane & 7);   // row 0..63

    __shared__ __align__(16) float buf[2][NN * RP];
    __shared__ __align__(16) float v[2][NN];
    __shared__ int is_last;

    const int m0 = (int)blockIdx.x;
    if (m0 < NMAT) issue_tile(buf[0], rc + (size_t)m0 * NN * NN, t);
    asm volatile("cp.async.commit_group;" ::: "memory");
    if (m0 + GRID_P < NMAT)
        issue_tile(buf[1], rc + (size_t)(m0 + GRID_P) * NN * NN, t);
    asm volatile("cp.async.commit_group;" ::: "memory");

#pragma unroll 1
    for (int i = 0, m = m0; m < NMAT; ++i, m += GRID_P) {
        const int s = m >> 6;
        asm volatile("cp.async.wait_group 1;" ::: "memory");
        __syncthreads();   // buf[i&1] ready; prior epilogue v-reads done

        // Uniform scalars early (from gmem: buf gets overwritten by prefetch).
        const float xw  = __ldg(x + m) * __ldg(wt + m);
        const float mss = __ldg(rc + (size_t)m * NN * NN + s * (NN + 1));

        // Row quarter [16q,16q+16) of pitched row k -> regs. Conflict-free.
        u64 row[8];
        {
            const float* bp = &buf[i & 1][k * RP + 16 * q];
#pragma unroll
            for (int j = 0; j < 4; ++j) {
                float4 f = *reinterpret_cast<const float4*>(bp + 4 * j);
                row[2 * j]     = pack(f.x, f.y);
                row[2 * j + 1] = pack(f.z, f.w);
            }
        }

        // Application 0: v0 = M*ones (scale irrelevant: output uses v[n]/v[s]).
        float vk;
        {
            u64 s0 = fadd2(fadd2(row[0], row[1]), fadd2(row[2], row[3]));
            u64 s1 = fadd2(fadd2(row[4], row[5]), fadd2(row[6], row[7]));
            u64 ss = fadd2(s0, s1);
            float2 f = *reinterpret_cast<float2*>(&ss);
            float p = f.x + f.y;
            p += __shfl_xor_sync(0xffffffffu, p, 8);
            p += __shfl_xor_sync(0xffffffffu, p, 16);
            vk = p;
            if (q == 0) v[0][k] = p;
        }
        __syncthreads();   // rows consumed by all + v[0] visible

        // Prefetch matrix m+2*GRID_P into the freed buffer (or empty group).
        if (m + 2 * GRID_P < NMAT)
            issue_tile(buf[i & 1], rc + (size_t)(m + 2 * GRID_P) * NN * NN, t);
        asm volatile("cp.async.commit_group;" ::: "memory");

#pragma unroll
        for (int it = 0; it < VAPPS; ++it) {
            // v window: phase-uniform broadcast loads.
            const float* vp = &v[it & 1][16 * q];
            float4 f0 = *reinterpret_cast<const float4*>(vp);
            float4 f1 = *reinterpret_cast<const float4*>(vp + 4);
            float4 f2 = *reinterpret_cast<const float4*>(vp + 8);
            float4 f3 = *reinterpret_cast<const float4*>(vp + 12);
            u64 a0 = ffma2(row[0], pack(f0.x, f0.y), 0ull);
            u64 a1 = ffma2(row[1], pack(f0.z, f0.w), 0ull);
            u64 a2 = ffma2(row[2], pack(f1.x, f1.y), 0ull);
            u64 a3 = ffma2(row[3], pack(f1.z, f1.w), 0ull);
            a0 = ffma2(row[4], pack(f2.x, f2.y), a0);
            a1 = ffma2(row[5], pack(f2.z, f2.w), a1);
            a2 = ffma2(row[6], pack(f3.x, f3.y), a2);
            a3 = ffma2(row[7], pack(f3.z, f3.w), a3);
            u64 ss = fadd2(fadd2(a0, a2), fadd2(a1, a3));
            float2 f = *reinterpret_cast<float2*>(&ss);
            float p = f.x + f.y;
            p += __shfl_xor_sync(0xffffffffu, p, 8);
            p += __shfl_xor_sync(0xffffffffu, p, 16);
            vk = p;
            if (q == 0) v[(it & 1) ^ 1][k] = p;   // it=3 writes v[0]
            __syncthreads();                      // ONE barrier per matvec
        }

        // Epilogue: vs broadcast from final v (in v[0]); q==0 lanes emit atomics.
        const float vs = v[0][s];
        if (q == 0)
            atomicAdd(&g_acc[k], xw * mss / vs * vk);
    }

    // Last block drains g_acc -> out and resets scratch (graph-replay safe).
    __threadfence();
    if (t == 0)
        is_last = (atomicAdd(&g_ticket, 1u) == (unsigned)(GRID_P - 1));
    __syncthreads();
    if (is_last) {
        if (t < NN) { out[t] = g_acc[t]; g_acc[t] = 0.0f; }
        if (t == 0) g_ticket = 0u;
    }
}

extern "C" void kernel_launch(void* const* d_in, const int* in_sizes, int n_in,
                              void* d_out, int out_size)
{
    // inputs: x, weights_t, weights_r (unused), r_zeros (all-zero), r_const
    const float* x  = (const float*)d_in[0];
    const float* wt = (const float*)d_in[1];
    const float* rc = (const float*)d_in[4];

    static bool carveout_set = false;
    if (!carveout_set) {
        cudaFuncSetAttribute(power_kernel,
                             cudaFuncAttributePreferredSharedMemoryCarveout, 100);
        carveout_set = true;
    }
    power_kernel<<<GRID_P, 256>>>(x, wt, rc, (float*)d_out);
}

// round 12
// speedup vs baseline: 1.2267x; 1.2267x over previous
#include <cuda_runtime.h>
#include <cstdint>

#define NN 64
#define NMAT 4096
#define GPB 4                     // 64-thread groups per 256-thread block
#define BLOCKS 304                // 2 blocks/SM x 152 SMs
#define NGROUPS (BLOCKS * GPB)    // 1216 independent pipelines
#define VAPPS 4                   // + rowsum init = 5 applications total
#define RP 68                     // tile row pitch (words): conflict-free
#define TILE_WORDS (NN * RP)      // 4352
#define SMEM_BYTES ((GPB * TILE_WORDS + GPB * 2 * NN) * 4)   // 71680

__device__ float g_acc[NN];
__device__ unsigned int g_ticket;

typedef unsigned long long u64;

__device__ __forceinline__ u64 ffma2(u64 a, u64 b, u64 c) {
    u64 d;
    asm("fma.rn.f32x2 %0, %1, %2, %3;" : "=l"(d) : "l"(a), "l"(b), "l"(c));
    return d;
}
__device__ __forceinline__ u64 fadd2(u64 a, u64 b) {
    u64 d;
    asm("add.rn.f32x2 %0, %1, %2;" : "=l"(d) : "l"(a), "l"(b));
    return d;
}
__device__ __forceinline__ u64 pack(float lo, float hi) {
    float2 f = make_float2(lo, hi);
    return *reinterpret_cast<u64*>(&f);
}
#define GBAR() asm volatile("bar.sync %0, 64;" :: "r"(barid) : "memory")

// Thread = one full row (zero cross-thread reduction). 4 independent
// 64-thread groups per block, each on its own named barrier -> 8 independent
// 2-warp pipelines per SM; no block-wide sync in the hot loop.
__global__ __launch_bounds__(256, 2)
void power_kernel(const float* __restrict__ x,
                  const float* __restrict__ wt,
                  const float* __restrict__ rc,
                  float* __restrict__ out)
{
    extern __shared__ float smem[];
    const int t  = threadIdx.x;
    const int g  = t >> 6;          // group 0..3
    const int tl = t & 63;          // row index within group's matrix
    const int barid = 1 + g;        // named barrier per group
    float* tile = smem + g * TILE_WORDS;
    float* vb   = smem + GPB * TILE_WORDS + g * 2 * NN;   // [2][64]

#pragma unroll 1
    for (int m = (int)blockIdx.x * GPB + g; m < NMAT; m += NGROUPS) {
        const float4* Mv =
            reinterpret_cast<const float4*>(rc + (size_t)m * (NN * NN));

        // Coalesced LDG.128 -> pitched STS.128 (both conflict-free).
#pragma unroll
        for (int j = 0; j < 16; ++j) {
            const int c = j * 64 + tl;          // 16B-chunk index
            float4 f = Mv[c];
            const int r = c >> 4, i2 = c & 15;
            *reinterpret_cast<float4*>(&tile[r * RP + 4 * i2]) = f;
        }
        GBAR();

        // Row tl -> regs (16 LDS.128, conflict-free via pitch 68).
        u64 row[32];
#pragma unroll
        for (int i = 0; i < 16; ++i) {
            float4 f = *reinterpret_cast<const float4*>(&tile[tl * RP + 4 * i]);
            row[2 * i]     = pack(f.x, f.y);
            row[2 * i + 1] = pack(f.z, f.w);
        }
        const int s = m >> 6;
        const float xw  = __ldg(x + m) * __ldg(wt + m);
        const float mss = tile[s * RP + s];     // pitched (s,s): word s*68+s

        // Application 0: v0 = M*ones = rowsum (scale of v is irrelevant:
        // the output uses v[n]/v[s]).
        float vk;
        {
            u64 a0 = row[0], a1 = row[1], a2 = row[2], a3 = row[3];
#pragma unroll
            for (int i = 4; i < 32; i += 4) {
                a0 = fadd2(a0, row[i]);     a1 = fadd2(a1, row[i + 1]);
                a2 = fadd2(a2, row[i + 2]); a3 = fadd2(a3, row[i + 3]);
            }
            u64 ss = fadd2(fadd2(a0, a1), fadd2(a2, a3));
            float2 f = *reinterpret_cast<float2*>(&ss);
            vk = f.x + f.y;
        }
        vb[tl] = vk;          // buffer 0
        GBAR();

        // 4 more applications; v double-buffered -> one group-barrier each.
#pragma unroll
        for (int it = 0; it < VAPPS; ++it) {
            const ulonglong2* vp =
                reinterpret_cast<const ulonglong2*>(vb + (it & 1) * NN);
            u64 a0 = 0, a1 = 0, a2 = 0, a3 = 0;
#pragma unroll
            for (int i = 0; i < 16; ++i) {
                ulonglong2 vv = vp[i];      // broadcast LDS.128 (uniform addr)
                if (i & 1) { a2 = ffma2(row[2 * i], vv.x, a2);
                             a3 = ffma2(row[2 * i + 1], vv.y, a3); }
                else       { a0 = ffma2(row[2 * i], vv.x, a0);
                             a1 = ffma2(row[2 * i + 1], vv.y, a1); }
            }
            u64 ss = fadd2(fadd2(a0, a2), fadd2(a1, a3));
            float2 f = *reinterpret_cast<float2*>(&ss);
            vk = f.x + f.y;
            vb[((it & 1) ^ 1) * NN + tl] = vk;
            GBAR();
        }

        // Final v is in buffer 0 (it=3 writes buf0); vk holds v[tl].
        const float vs = vb[s];
        atomicAdd(&g_acc[tl], xw * mss / vs * vk);
        GBAR();   // protect vb buf0 reads before next matrix's rowsum write
    }

    // Drain: last block copies g_acc -> out and resets scratch.
    __threadfence();
    __syncthreads();
    __shared__ int is_last;
    if (t == 0)
        is_last = (atomicAdd(&g_ticket, 1u) == (unsigned)(BLOCKS - 1));
    __syncthreads();
    if (is_last) {
        if (t < NN) { out[t] = g_acc[t]; g_acc[t] = 0.0f; }
        if (t == 0) g_ticket = 0u;
    }
}

extern "C" void kernel_launch(void* const* d_in, const int* in_sizes, int n_in,
                              void* d_out, int out_size)
{
    // inputs: x, weights_t, weights_r (unused), r_zeros (all-zero), r_const
    const float* x  = (const float*)d_in[0];
    const float* wt = (const float*)d_in[1];
    const float* rc = (const float*)d_in[4];

    static bool attr_set = false;
    if (!attr_set) {
        cudaFuncSetAttribute(power_kernel,
                             cudaFuncAttributeMaxDynamicSharedMemorySize,
                             SMEM_BYTES);
        cudaFuncSetAttribute(power_kernel,
                             cudaFuncAttributePreferredSharedMemoryCarveout, 100);
        attr_set = true;
    }
    power_kernel<<<BLOCKS, 256, SMEM_BYTES>>>(x, wt, rc, (float*)d_out);
}